// round 9
// baseline (speedup 1.0000x reference)
#include <cuda_runtime.h>

typedef unsigned long long ull;

__device__ __forceinline__ ull pk(float lo, float hi) {
    ull r; asm("mov.b64 %0, {%1,%2};" : "=l"(r) : "f"(lo), "f"(hi)); return r;
}
__device__ __forceinline__ void upk(ull v, float &lo, float &hi) {
    asm("mov.b64 {%0,%1}, %2;" : "=f"(lo), "=f"(hi) : "l"(v));
}
__device__ __forceinline__ ull f2fma(ull a, ull b, ull c) {
    ull d; asm("fma.rn.f32x2 %0,%1,%2,%3;" : "=l"(d) : "l"(a), "l"(b), "l"(c)); return d;
}

// ===========================================================================
// Fused kernel, 256 blocks x 128 threads (~2 blocks/SM for cross-block
// latency hiding). Block = 64 tokens = 8 (b,s) rows.
//   warps 0-1 : 1 token/thread -> closed-form q (Pauli sweep, R4-validated)
//   warps 2-3 : W LDG (16 float4/thread) -> swizzled shared ; fast params
//   phase 2   : all 4 warps, f32x2 packed dot products (4 outputs/thread)
// ===========================================================================
__global__ void __launch_bounds__(128) qmha_fused(const float* __restrict__ x,
                                                  const float* __restrict__ prx,
                                                  const float* __restrict__ prz,
                                                  const float* __restrict__ W,
                                                  float* __restrict__ out) {
    __shared__ float s_rx0[8], s_sf[8], s_cf[8], s_c1[8], s_s1[8];
    __shared__ float4 Ws4[1024];   // W float4 (j,c) at slot j*16 + (c ^ (j&7))
    __shared__ float qs[512];      // 8 rows x 64

    int tid = threadIdx.x;
    float4 xa, xb;
    float4 wreg[16];

    if (tid < 64) {
        // token threads: x in flight immediately
        int t = blockIdx.x * 64 + tid;
        const float4* xp = reinterpret_cast<const float4*>(x + t * 8);
        xa = __ldg(xp); xb = __ldg(xp + 1);
    } else {
        int wt = tid - 64;
        const float4* Wg = reinterpret_cast<const float4*>(W);
#pragma unroll
        for (int i = 0; i < 16; i++) wreg[i] = __ldg(Wg + wt + i * 64);
        if (wt < 8) {
            s_rx0[wt] = __ldg(prx + wt);
            float s, c; __sincosf(__ldg(prz + wt), &s, &c);    // layer-0 RZ
            s_sf[wt] = s; s_cf[wt] = c;
        } else if (wt < 16) {
            int i = wt - 8;
            float s, c; __sincosf(__ldg(prx + 8 + i), &s, &c); // layer-1 RX
            s_s1[i] = s; s_c1[i] = c;
        }
    }
    __syncthreads();   // params ready (overlapped with x LDG latency)

    if (tid < 64) {
        // ---- Phase 1: closed-form q for this thread's token ----
        float xv[8] = {xa.x, xa.y, xa.z, xa.w, xb.x, xb.y, xb.z, xb.w};
        float vx[8], vy[8], vz[8];
#pragma unroll
        for (int w = 0; w < 8; w++) {
            float st, ct;
            __sincosf(xv[w] + s_rx0[w], &st, &ct);
            vz[w] = ct;
            vx[w] = st * s_sf[w];
            vy[w] = -st * s_cf[w];
        }

        // A_0: after CNOT(0,1); rows = pending wire-0 Pauli, cols = carry
        float A[4][4];
        A[0][0] = 1.f;            A[0][1] = vx[1];          A[0][2] = vz[0] * vy[1];  A[0][3] = vz[0] * vz[1];
        A[1][0] = vx[0] * vx[1];  A[1][1] = vx[0];          A[1][2] = vy[0] * vz[1];  A[1][3] = -vy[0] * vy[1];
        A[2][0] = vy[0] * vx[1];  A[2][1] = vy[0];          A[2][2] = -vx[0] * vz[1]; A[2][3] = vx[0] * vy[1];
        A[3][0] = vz[0];          A[3][1] = vz[0] * vx[1];  A[3][2] = vy[1];          A[3][3] = vz[1];

        float Zt[7];
        Zt[6] = 1.f;
#pragma unroll
        for (int k = 5; k >= 1; k--) Zt[k] = Zt[k + 1] * vz[k + 2];

        float q[8];
        float c10 = s_c1[0], s10 = s_s1[0];
#pragma unroll
        for (int w = 1; w <= 6; w++) {
            float cc = s_c1[w], ss = s_s1[w];
            float xn = vx[w + 1], yn = vy[w + 1], zn = vz[w + 1];
            float cx = cc * xn, cy = cc * yn, cz = cc * zn;
            float sx = ss * xn, sy = ss * yn, sz = ss * zn;
#pragma unroll
            for (int r = 0; r < 4; r++) {
                float aI = A[r][0], aX = A[r][1], aY = A[r][2], aZ = A[r][3];
                A[r][0] = cc * aZ + sx * aY;
                A[r][1] = cx * aZ + ss * aY;
                A[r][2] = cy * aI - sz * aX;
                A[r][3] = cz * aI + sy * aX;
            }
            q[w] = Zt[w] * (s10 * A[2][3] + c10 * A[3][3]);
        }
        float c17 = s_c1[7], s17 = s_s1[7];
        q[7] = c17 * (s10 * A[2][0] + c10 * A[3][0]) + s17 * (c10 * A[2][1] - s10 * A[3][1]);
        q[0] = c17 * A[0][3] + s17 * A[1][2];

        // qs[tid*8+w] == row-major [row_local=tid/8][k=(tid%8)*8+w]
        float4* qo = reinterpret_cast<float4*>(qs + tid * 8);
        qo[0] = make_float4(q[0], q[1], q[2], q[3]);
        qo[1] = make_float4(q[4], q[5], q[6], q[7]);
    } else {
        // ---- park W into swizzled shared (loads landed during phase 1) ----
        int wt = tid - 64;
#pragma unroll
        for (int i = 0; i < 16; i++) {
            int m = wt + i * 64;            // float4 index = j*16 + c
            int j = m >> 4, c = m & 15;
            Ws4[j * 16 + (c ^ (j & 7))] = wreg[i];
        }
    }
    __syncthreads();

    // ---- Phase 2: 4 outputs/thread, f32x2 packed MACs ----
    int j = tid & 63, g = tid >> 6;        // col j; rows g*4 .. g*4+3
    const float4* q4 = reinterpret_cast<const float4*>(qs) + g * 64;

    ull acc[4] = {0, 0, 0, 0};
#pragma unroll
    for (int c = 0; c < 16; c++) {
        float4 wv = Ws4[j * 16 + (c ^ (j & 7))];   // conflict-free (swizzled)
        ull w01 = pk(wv.x, wv.y), w23 = pk(wv.z, wv.w);
#pragma unroll
        for (int r = 0; r < 4; r++) {
            float4 a = q4[r * 16 + c];             // warp-broadcast LDS
            acc[r] = f2fma(pk(a.x, a.y), w01, acc[r]);
            acc[r] = f2fma(pk(a.z, a.w), w23, acc[r]);
        }
    }
    int row0 = blockIdx.x * 8 + g * 4;
#pragma unroll
    for (int r = 0; r < 4; r++) {
        float lo, hi; upk(acc[r], lo, hi);
        out[(row0 + r) * 64 + j] = lo + hi;
    }
}

extern "C" void kernel_launch(void* const* d_in, const int* in_sizes, int n_in,
                              void* d_out, int out_size) {
    const float* x   = (const float*)d_in[0];
    const float* prx = (const float*)d_in[1];
    const float* prz = (const float*)d_in[2];
    const float* W   = (const float*)d_in[3];
    float* out = (float*)d_out;

    int n_tok = in_sizes[0] / 8;                    // 16384 tokens
    qmha_fused<<<n_tok / 64, 128>>>(x, prx, prz, W, out);   // 256 blocks
}

// round 10
// speedup vs baseline: 1.1014x; 1.1014x over previous
#include <cuda_runtime.h>

typedef unsigned long long ull;

__device__ __forceinline__ ull pk(float lo, float hi) {
    ull r; asm("mov.b64 %0, {%1,%2};" : "=l"(r) : "f"(lo), "f"(hi)); return r;
}
__device__ __forceinline__ void upk(ull v, float &lo, float &hi) {
    asm("mov.b64 {%0,%1}, %2;" : "=f"(lo), "=f"(hi) : "l"(v));
}
__device__ __forceinline__ ull f2fma(ull a, ull b, ull c) {
    ull d; asm("fma.rn.f32x2 %0,%1,%2,%3;" : "=l"(d) : "l"(a), "l"(b), "l"(c)); return d;
}

// ===========================================================================
// Fused single-wave kernel, ONE barrier. 128 blocks x 256 threads.
//   warps 0-3 : 1 token/thread; params self-loaded (same MLP batch as x) and
//               self-computed -> no param barrier. Closed-form Pauli sweep.
//   warps 4-7 : pure W LDG -> swizzled shared pipeline.
//   phase 2   : all 8 warps, f32x2 packed dot products (4 outputs/thread).
// ===========================================================================
__global__ void __launch_bounds__(256) qmha_fused(const float* __restrict__ x,
                                                  const float* __restrict__ prx,
                                                  const float* __restrict__ prz,
                                                  const float* __restrict__ W,
                                                  float* __restrict__ out) {
    __shared__ float4 Ws4[1024];   // W float4 (j,c) at slot j*16 + (c ^ (j&7))
    __shared__ float qs[1024];     // 16 rows x 64

    int tid = threadIdx.x;

    if (tid < 128) {
        // ---- token thread: batch ALL loads up front (x + params, MLP 8) ----
        int t = blockIdx.x * 128 + tid;
        const float4* xp = reinterpret_cast<const float4*>(x + t * 8);
        const float4* prx4 = reinterpret_cast<const float4*>(prx);
        const float4* prz4 = reinterpret_cast<const float4*>(prz);
        float4 xa = __ldg(xp), xb = __ldg(xp + 1);
        float4 p0 = __ldg(prx4),     p1 = __ldg(prx4 + 1);   // prx[0..7]  (layer-0 RX)
        float4 p2 = __ldg(prx4 + 2), p3 = __ldg(prx4 + 3);   // prx[8..15] (layer-1 RX)
        float4 z0 = __ldg(prz4),     z1 = __ldg(prz4 + 1);   // prz[0..7]  (layer-0 RZ)

        float xv[8] = {xa.x, xa.y, xa.z, xa.w, xb.x, xb.y, xb.z, xb.w};
        float a0[8] = {p0.x, p0.y, p0.z, p0.w, p1.x, p1.y, p1.z, p1.w};
        float g1[8] = {p2.x, p2.y, p2.z, p2.w, p3.x, p3.y, p3.z, p3.w};
        float ph[8] = {z0.x, z0.y, z0.z, z0.w, z1.x, z1.y, z1.z, z1.w};

        // Wire Bloch vectors + layer-1 RX cos/sin, all via fast MUFU path
        float vx[8], vy[8], vz[8], c1[8], s1[8];
#pragma unroll
        for (int w = 0; w < 8; w++) {
            float st, ct, sf, cf;
            __sincosf(xv[w] + a0[w], &st, &ct);
            __sincosf(ph[w], &sf, &cf);
            __sincosf(g1[w], &s1[w], &c1[w]);
            vz[w] = ct;
            vx[w] = st * sf;
            vy[w] = -st * cf;
        }

        // A_0: after CNOT(0,1); rows = pending wire-0 Pauli, cols = carry
        float A[4][4];
        A[0][0] = 1.f;            A[0][1] = vx[1];          A[0][2] = vz[0] * vy[1];  A[0][3] = vz[0] * vz[1];
        A[1][0] = vx[0] * vx[1];  A[1][1] = vx[0];          A[1][2] = vy[0] * vz[1];  A[1][3] = -vy[0] * vy[1];
        A[2][0] = vy[0] * vx[1];  A[2][1] = vy[0];          A[2][2] = -vx[0] * vz[1]; A[2][3] = vx[0] * vy[1];
        A[3][0] = vz[0];          A[3][1] = vz[0] * vx[1];  A[3][2] = vy[1];          A[3][3] = vz[1];

        float Zt[7];
        Zt[6] = 1.f;
#pragma unroll
        for (int k = 5; k >= 1; k--) Zt[k] = Zt[k + 1] * vz[k + 2];

        float q[8];
        float c10 = c1[0], s10 = s1[0];
#pragma unroll
        for (int w = 1; w <= 6; w++) {
            float cc = c1[w], ss = s1[w];
            float xn = vx[w + 1], yn = vy[w + 1], zn = vz[w + 1];
            float cx = cc * xn, cy = cc * yn, cz = cc * zn;
            float sx = ss * xn, sy = ss * yn, sz = ss * zn;
#pragma unroll
            for (int r = 0; r < 4; r++) {
                float aI = A[r][0], aX = A[r][1], aY = A[r][2], aZ = A[r][3];
                A[r][0] = cc * aZ + sx * aY;
                A[r][1] = cx * aZ + ss * aY;
                A[r][2] = cy * aI - sz * aX;
                A[r][3] = cz * aI + sy * aX;
            }
            q[w] = Zt[w] * (s10 * A[2][3] + c10 * A[3][3]);
        }
        float c17 = c1[7], s17 = s1[7];
        q[7] = c17 * (s10 * A[2][0] + c10 * A[3][0]) + s17 * (c10 * A[2][1] - s10 * A[3][1]);
        q[0] = c17 * A[0][3] + s17 * A[1][2];

        // qs[tid*8+w] == row-major [row_local=tid/8][k=(tid%8)*8+w]
        float4* qo = reinterpret_cast<float4*>(qs + tid * 8);
        qo[0] = make_float4(q[0], q[1], q[2], q[3]);
        qo[1] = make_float4(q[4], q[5], q[6], q[7]);
    } else {
        // ---- W warp: pure LDG -> swizzled STS pipeline ----
        int wt = tid - 128;
        const float4* Wg = reinterpret_cast<const float4*>(W);
        float4 wreg[8];
#pragma unroll
        for (int i = 0; i < 8; i++) wreg[i] = __ldg(Wg + wt + i * 128);
#pragma unroll
        for (int i = 0; i < 8; i++) {
            int m = wt + i * 128;           // float4 index = j*16 + c
            int j = m >> 4, c = m & 15;
            Ws4[j * 16 + (c ^ (j & 7))] = wreg[i];
        }
    }
    __syncthreads();   // the ONLY barrier

    // ---- Phase 2: 4 outputs/thread, f32x2 packed MACs ----
    int j = tid & 63, g = tid >> 6;        // col j; rows g*4 .. g*4+3
    const float4* q4 = reinterpret_cast<const float4*>(qs) + g * 64;

    ull acc[4] = {0, 0, 0, 0};
#pragma unroll
    for (int c = 0; c < 16; c++) {
        float4 wv = Ws4[j * 16 + (c ^ (j & 7))];   // conflict-free (swizzled)
        ull w01 = pk(wv.x, wv.y), w23 = pk(wv.z, wv.w);
#pragma unroll
        for (int r = 0; r < 4; r++) {
            float4 a = q4[r * 16 + c];             // warp-broadcast LDS
            acc[r] = f2fma(pk(a.x, a.y), w01, acc[r]);
            acc[r] = f2fma(pk(a.z, a.w), w23, acc[r]);
        }
    }
    int row0 = blockIdx.x * 16 + g * 4;
#pragma unroll
    for (int r = 0; r < 4; r++) {
        float lo, hi; upk(acc[r], lo, hi);
        out[(row0 + r) * 64 + j] = lo + hi;
    }
}

extern "C" void kernel_launch(void* const* d_in, const int* in_sizes, int n_in,
                              void* d_out, int out_size) {
    const float* x   = (const float*)d_in[0];
    const float* prx = (const float*)d_in[1];
    const float* prz = (const float*)d_in[2];
    const float* W   = (const float*)d_in[3];
    float* out = (float*)d_out;

    int n_tok = in_sizes[0] / 8;                    // 16384 tokens
    qmha_fused<<<n_tok / 128, 256>>>(x, prx, prz, W, out);  // 128 blocks, 1 wave
}